// round 15
// baseline (speedup 1.0000x reference)
#include <cuda_runtime.h>
#include <cuda_bf16.h>
#include <math.h>
#include <stdint.h>

#define NB 256
#define NR 1152
#define NC2 10
#define LDA 40
#define BUFB 40960
#define BUFE 20480
#define XROWS 1792          // 64 guard + 1600 grid + 128 guard

__device__ __forceinline__ void mma16816(float* d, unsigned a0, unsigned a1, unsigned a2, unsigned a3,
                                         unsigned b0, unsigned b1) {
    asm volatile("mma.sync.aligned.m16n8k16.row.col.f32.bf16.bf16.f32 "
        "{%0,%1,%2,%3}, {%4,%5,%6,%7}, {%8,%9}, {%0,%1,%2,%3};"
        : "+f"(d[0]), "+f"(d[1]), "+f"(d[2]), "+f"(d[3])
        : "r"(a0), "r"(a1), "r"(a2), "r"(a3), "r"(b0), "r"(b1));
}
__device__ __forceinline__ void ldsm_x4(unsigned* r, uint32_t addr) {
    asm volatile("ldmatrix.sync.aligned.m8n8.x4.shared.b16 {%0,%1,%2,%3}, [%4];"
        : "=r"(r[0]), "=r"(r[1]), "=r"(r[2]), "=r"(r[3]) : "r"(addr));
}
__device__ __forceinline__ void bfsplit(float f, __nv_bfloat16& h, __nv_bfloat16& l) {
    h = __float2bfloat16(f);
    l = __float2bfloat16(f - __bfloat162float(h));
}
__device__ __forceinline__ void cp16(uint32_t dst, const void* src) {
    asm volatile("cp.async.ca.shared.global [%0], [%1], 16;" :: "r"(dst), "l"(src));
}
__device__ __forceinline__ void cp_commit() {
    asm volatile("cp.async.commit_group;" ::: "memory");
}
__device__ __forceinline__ void cp_wait() {
    asm volatile("cp.async.wait_group 0;" ::: "memory");
}

// ---- scratch ----
__device__ __nv_bfloat16 g_xh[(size_t)NB * XROWS * 64];   // conv1 out, padded position-major
__device__ __nv_bfloat16 g_xl[(size_t)NB * XROWS * 64];
__device__ float g_c2[(size_t)NB * 1444 * 128];
__device__ __nv_bfloat16 g_p2h[(size_t)NB * 400 * 128];   // pool2 position-major
__device__ __nv_bfloat16 g_p2l[(size_t)NB * 400 * 128];
__device__ __nv_bfloat16 g_wsh[9 * 128 * 64];             // conv2 W [shift][oc][ic]
__device__ __nv_bfloat16 g_wsl[9 * 128 * 64];
__device__ __nv_bfloat16 g_psh[(size_t)81 * 256 * 128];   // prim W [shift][oc][ic]
__device__ __nv_bfloat16 g_psl[(size_t)81 * 256 * 128];
__device__ float g_upart[(size_t)4 * NB * 9216];
__device__ float g_u[(size_t)NB * 9216];
__device__ float4 g_uhat4[(size_t)NB * NR * NC2 * 4];
__device__ float g_bij[NR * NC2];
__device__ float g_cij[NR * NC2];
__device__ float4 g_v4[NB * NC2 * 4];
#define G_UHAT ((float*)g_uhat4)
#define G_V ((float*)g_v4)

__global__ void k_cvt_w2(const float* __restrict__ w2) {
    int i = blockIdx.x * blockDim.x + threadIdx.x;       // 73728
    if (i >= 9 * 128 * 64) return;
    int s = i >> 13, rem = i & 8191;
    int oc = rem >> 6, ic = rem & 63;
    __nv_bfloat16 h, l; bfsplit(w2[oc * 576 + ic * 9 + s], h, l);
    g_wsh[i] = h; g_wsl[i] = l;
}
__global__ void k_cvt_pw(const float* __restrict__ pw) {
    int i = blockIdx.x * blockDim.x + threadIdx.x;       // 2654208
    int s = i >> 15, rem = i & 32767;
    int oc = rem >> 7, ic = rem & 127;
    __nv_bfloat16 h, l; bfsplit(pw[(size_t)oc * 10368 + ic * 81 + s], h, l);
    g_psh[i] = h; g_psl[i] = l;
}

// ---- conv1+relu+pool -> padded position-major planes ----
__global__ void __launch_bounds__(256) k_conv1pool(const float* __restrict__ data,
                                                   const float* __restrict__ w1,
                                                   const float* __restrict__ b1) {
    __shared__ float sw[1728];
    __shared__ float sb[64];
    int tid = threadIdx.x;
    for (int i = tid; i < 1728; i += 256) sw[i] = w1[i];
    if (tid < 64) sb[tid] = b1[tid];
    __syncthreads();

    int idx = blockIdx.x * blockDim.x + tid;
    int p = idx % 1444, b = idx / 1444;
    int pj = p / 38, pi = p % 38;
    int y0 = 2 * pj - 1, x0 = 2 * pi - 1;
    float iv[3][4][4];
#pragma unroll
    for (int ic = 0; ic < 3; ic++)
#pragma unroll
        for (int dy = 0; dy < 4; dy++) {
            int yy = y0 + dy;
#pragma unroll
            for (int dx = 0; dx < 4; dx++) {
                int xx = x0 + dx;
                float v = 0.f;
                if (yy >= 0 && yy < 76 && xx >= 0 && xx < 76)
                    v = data[((size_t)(b * 3 + ic) * 76 + yy) * 76 + xx];
                iv[ic][dy][dx] = v;
            }
        }
    bool rv0 = (y0 >= 0), rv1 = (y0 + 1 <= 73), cv0 = (x0 >= 0), cv1 = (x0 + 1 <= 73);
    size_t xb = ((size_t)b * XROWS + 64 + (pj + 1) * 40 + pi + 1) * 64;
#pragma unroll 1
    for (int oc = 0; oc < 64; oc += 2) {
        const float* wa = sw + oc * 27;
        const float* wb = wa + 27;
        float a00 = 0.f, a01 = 0.f, a10 = 0.f, a11 = 0.f;
        float c00 = 0.f, c01 = 0.f, c10 = 0.f, c11 = 0.f;
#pragma unroll
        for (int k = 0; k < 27; k++) {
            int ic = k / 9, r = (k / 3) % 3, c2 = k % 3;
            float v00 = iv[ic][r][c2], v01 = iv[ic][r][c2 + 1];
            float v10 = iv[ic][r + 1][c2], v11 = iv[ic][r + 1][c2 + 1];
            float wA = wa[k], wB = wb[k];
            a00 = fmaf(v00, wA, a00); a01 = fmaf(v01, wA, a01);
            a10 = fmaf(v10, wA, a10); a11 = fmaf(v11, wA, a11);
            c00 = fmaf(v00, wB, c00); c01 = fmaf(v01, wB, c01);
            c10 = fmaf(v10, wB, c10); c11 = fmaf(v11, wB, c11);
        }
        float boA = sb[oc], boB = sb[oc + 1];
        float mA = 0.f, mB = 0.f;
        if (rv0 && cv0) { mA = fmaxf(mA, a00 + boA); mB = fmaxf(mB, c00 + boB); }
        if (rv0 && cv1) { mA = fmaxf(mA, a01 + boA); mB = fmaxf(mB, c01 + boB); }
        if (rv1 && cv0) { mA = fmaxf(mA, a10 + boA); mB = fmaxf(mB, c10 + boB); }
        if (rv1 && cv1) { mA = fmaxf(mA, a11 + boA); mB = fmaxf(mB, c11 + boB); }
        __nv_bfloat16 h, l;
        bfsplit(mA, h, l); g_xh[xb + oc] = h; g_xl[xb + oc] = l;
        bfsplit(mB, h, l); g_xh[xb + oc + 1] = h; g_xl[xb + oc + 1] = l;
    }
}

// ---- gemm: warp tile M=32 x N=64 ----
__device__ __forceinline__ void gemm_chunk(float acc[16][4], uint32_t aH, uint32_t aL,
                                           uint32_t bH, uint32_t bL) {
#pragma unroll
    for (int ks = 0; ks < 2; ks++) {
        unsigned Ah[2][4], Al[2][4];
        ldsm_x4(Ah[0], aH + ks * 32);
        ldsm_x4(Ah[1], aH + 16 * LDA * 2 + ks * 32);
        ldsm_x4(Al[0], aL + ks * 32);
        ldsm_x4(Al[1], aL + 16 * LDA * 2 + ks * 32);
#pragma unroll
        for (int j = 0; j < 4; j++) {
            unsigned Bh[4], Bl[4];
            uint32_t bo = (uint32_t)j * (16 * LDA * 2) + ks * 32;
            ldsm_x4(Bh, bH + bo);
            ldsm_x4(Bl, bL + bo);
#pragma unroll
            for (int mt = 0; mt < 2; mt++) {
                int t0 = mt * 8 + j * 2;
                mma16816(acc[t0],     Ah[mt][0], Ah[mt][1], Ah[mt][2], Ah[mt][3], Bh[0], Bh[1]);
                mma16816(acc[t0],     Al[mt][0], Al[mt][1], Al[mt][2], Al[mt][3], Bh[0], Bh[1]);
                mma16816(acc[t0],     Ah[mt][0], Ah[mt][1], Ah[mt][2], Ah[mt][3], Bl[0], Bl[1]);
                mma16816(acc[t0 + 1], Ah[mt][0], Ah[mt][1], Ah[mt][2], Ah[mt][3], Bh[2], Bh[3]);
                mma16816(acc[t0 + 1], Al[mt][0], Al[mt][1], Al[mt][2], Al[mt][3], Bh[2], Bh[3]);
                mma16816(acc[t0 + 1], Ah[mt][0], Ah[mt][1], Ah[mt][2], Ah[mt][3], Bl[2], Bl[3]);
            }
        }
    }
}

// ---- conv2 as 9 shifted GEMMs; all staging via cp.async ----
__global__ void __launch_bounds__(256, 2) k_conv2mma(const float* __restrict__ b2) {
    extern __shared__ __nv_bfloat16 sm[];
    int tid = threadIdx.x;
    int w = tid >> 5, lane = tid & 31;
    int g = lane >> 2, tg = lane & 3;
    int wm = w & 3, wn = w >> 2;
    int bb = blockIdx.y, strip = blockIdx.x;

    uint32_t smb = (uint32_t)__cvta_generic_to_shared(sm);
    uint32_t aoff = ((unsigned)(wm * 32 + (lane & 15)) * LDA + ((lane & 16) ? 8 : 0)) * 2;
    uint32_t boff = ((unsigned)(wn * 64 + (lane & 7) + ((lane & 16) ? 8 : 0)) * LDA + ((lane & 8) ? 8 : 0)) * 2;

    float acc[16][4];
#pragma unroll
    for (int n = 0; n < 16; n++)
#pragma unroll
        for (int q = 0; q < 4; q++) acc[n][q] = 0.f;

    int rr = tid & 127, plane = tid >> 7;
    const __nv_bfloat16* aplane = plane ? g_xl : g_xh;
    const __nv_bfloat16* bplane = plane ? g_wsl : g_wsh;
    size_t arowbase = ((size_t)bb * XROWS + 64 + strip * 128 + rr) * 64;
    uint32_t adst0 = smb + (unsigned)plane * 10240 + (unsigned)rr * 80;
    uint32_t bdst0 = smb + 20480 + (unsigned)plane * 10240 + (unsigned)rr * 80;

    auto stage = [&](int kc, int buf) {
        int s = kc >> 1, hh = kc & 1;
        int shoff = (s / 3 - 1) * 40 + (s % 3) - 1;
        const __nv_bfloat16* asrc = aplane + arowbase + (ptrdiff_t)shoff * 64 + hh * 32;
        const __nv_bfloat16* bsrc = bplane + s * 8192 + rr * 64 + hh * 32;
        uint32_t ad = adst0 + buf * BUFB, bd = bdst0 + buf * BUFB;
#pragma unroll
        for (int seg = 0; seg < 4; seg++) {
            cp16(ad + seg * 16, asrc + seg * 8);
            cp16(bd + seg * 16, bsrc + seg * 8);
        }
        cp_commit();
    };

    stage(0, 0);
    cp_wait();
    __syncthreads();

#pragma unroll 1
    for (int kc = 0; kc < 18; kc++) {
        int nxt = kc + 1;
        if (nxt < 18) stage(nxt, nxt & 1);
        uint32_t base = smb + (kc & 1) * BUFB;
        gemm_chunk(acc, base + aoff, base + 10240 + aoff,
                        base + 20480 + boff, base + 30720 + boff);
        cp_wait();
        __syncthreads();
    }

#pragma unroll
    for (int mt = 0; mt < 2; mt++) {
        int pp0 = strip * 128 + wm * 32 + mt * 16 + g;
        int pp1 = pp0 + 8;
        int y0 = pp0 / 40, x0 = pp0 % 40;
        int y1 = pp1 / 40, x1 = pp1 % 40;
        bool v0 = (y0 >= 1 && y0 <= 38 && x0 >= 1 && x0 <= 38);
        bool v1 = (y1 >= 1 && y1 <= 38 && x1 >= 1 && x1 <= 38);
        int p0 = (y0 - 1) * 38 + x0 - 1;
        int p1 = (y1 - 1) * 38 + x1 - 1;
#pragma unroll
        for (int j = 0; j < 4; j++)
#pragma unroll
            for (int h = 0; h < 2; h++) {
                int t = mt * 8 + j * 2 + h;
                int col = wn * 64 + j * 16 + h * 8 + tg * 2;
                float bc0 = __ldg(b2 + col), bc1 = __ldg(b2 + col + 1);
                if (v0) {
                    float2 o; o.x = fmaxf(acc[t][0] + bc0, 0.f); o.y = fmaxf(acc[t][1] + bc1, 0.f);
                    *(float2*)(g_c2 + ((size_t)bb * 1444 + p0) * 128 + col) = o;
                }
                if (v1) {
                    float2 o; o.x = fmaxf(acc[t][2] + bc0, 0.f); o.y = fmaxf(acc[t][3] + bc1, 0.f);
                    *(float2*)(g_c2 + ((size_t)bb * 1444 + p1) * 128 + col) = o;
                }
            }
    }
}

// ---- maxpool -> position-major h/l planes ----
__global__ void __launch_bounds__(256) k_pool2n() {
    size_t idx = (size_t)blockIdx.x * 256 + threadIdx.x;   // NB*400*128
    int oc = idx & 127;
    int p2 = (idx >> 7) % 400;
    int b = (int)(idx >> 7) / 400;
    int pj = p2 / 20, pi = p2 % 20;
    int y0 = 2 * pj - 1, x0 = 2 * pi - 1;
    float m = 0.f;
#pragma unroll
    for (int dy = 0; dy < 2; dy++) {
        int y = y0 + dy; if (y < 0 || y > 37) continue;
#pragma unroll
        for (int dx = 0; dx < 2; dx++) {
            int x = x0 + dx; if (x < 0 || x > 37) continue;
            m = fmaxf(m, g_c2[((size_t)b * 1444 + y * 38 + x) * 128 + oc]);
        }
    }
    __nv_bfloat16 h, l; bfsplit(m, h, l);
    g_p2h[idx] = h; g_p2l[idx] = l;
}

// ---- PrimaryCaps as 81 shifted GEMMs, K-split x4 ----
__global__ void __launch_bounds__(256, 2) k_primmma() {
    extern __shared__ __nv_bfloat16 sm[];
    int tid = threadIdx.x;
    int w = tid >> 5, lane = tid & 31;
    int g = lane >> 2, tg = lane & 3;
    int wm = w & 3, wn = w >> 2;
    int mb = blockIdx.x, ny = blockIdx.y, zz = blockIdx.z;

    uint32_t smb = (uint32_t)__cvta_generic_to_shared(sm);
    uint32_t aoff = ((unsigned)(wm * 32 + (lane & 15)) * LDA + ((lane & 16) ? 8 : 0)) * 2;
    uint32_t boff = ((unsigned)(wn * 64 + (lane & 7) + ((lane & 16) ? 8 : 0)) * LDA + ((lane & 8) ? 8 : 0)) * 2;

    float acc[16][4];
#pragma unroll
    for (int n = 0; n < 16; n++)
#pragma unroll
        for (int q = 0; q < 4; q++) acc[n][q] = 0.f;

    int rr = tid & 127, plane = tid >> 7;
    int mA = mb * 128 + rr;
    int bA = mA / 36, posA = mA % 36;
    int sjA = posA / 6, siA = posA % 6;
    const __nv_bfloat16* aplane = plane ? g_p2l : g_p2h;
    const __nv_bfloat16* bplane = plane ? g_psl : g_psh;
    size_t arowbase = ((size_t)bA * 400 + sjA * 40 + siA * 2) * 128;
    uint32_t adst0 = smb + (unsigned)plane * 10240 + (unsigned)rr * 80;
    uint32_t bdst0 = smb + 20480 + (unsigned)plane * 10240 + (unsigned)rr * 80;

    auto stage = [&](int kc, int buf) {
        int s = kc >> 2, qq = kc & 3;
        const __nv_bfloat16* asrc = aplane + arowbase + ((s / 9) * 20 + (s % 9)) * 128 + qq * 32;
        const __nv_bfloat16* bsrc = bplane + (size_t)s * 32768 + (ny * 128 + rr) * 128 + qq * 32;
        uint32_t ad = adst0 + buf * BUFB, bd = bdst0 + buf * BUFB;
#pragma unroll
        for (int seg = 0; seg < 4; seg++) {
            cp16(ad + seg * 16, asrc + seg * 8);
            cp16(bd + seg * 16, bsrc + seg * 8);
        }
        cp_commit();
    };

    int kc0 = zz * 81, kc1 = kc0 + 81;
    stage(kc0, 0);
    cp_wait();
    __syncthreads();

#pragma unroll 1
    for (int kc = kc0; kc < kc1; kc++) {
        int nxt = kc + 1;
        if (nxt < kc1) stage(nxt, (nxt - kc0) & 1);
        uint32_t base = smb + ((kc - kc0) & 1) * BUFB;
        gemm_chunk(acc, base + aoff, base + 10240 + aoff,
                        base + 20480 + boff, base + 30720 + boff);
        cp_wait();
        __syncthreads();
    }

    float* up = g_upart + (size_t)zz * NB * 9216;
#pragma unroll
    for (int mt = 0; mt < 2; mt++) {
        int m0 = mb * 128 + wm * 32 + mt * 16 + g;
        int m1 = m0 + 8;
        int b0 = m0 / 36, pos0 = m0 % 36;
        int b1i = m1 / 36, pos1 = m1 % 36;
#pragma unroll
        for (int j = 0; j < 4; j++)
#pragma unroll
            for (int h = 0; h < 2; h++) {
                int t = mt * 8 + j * 2 + h;
                int col = ny * 128 + wn * 64 + j * 16 + h * 8 + tg * 2;
                up[(size_t)b0 * 9216 + (size_t)col * 36 + pos0] = acc[t][0];
                up[(size_t)b0 * 9216 + (size_t)(col + 1) * 36 + pos0] = acc[t][1];
                up[(size_t)b1i * 9216 + (size_t)col * 36 + pos1] = acc[t][2];
                up[(size_t)b1i * 9216 + (size_t)(col + 1) * 36 + pos1] = acc[t][3];
            }
    }
}

// ---- squash: sum 4 K-slices + bias ----
__global__ void k_squash(const float* __restrict__ pb) {
    int idx = blockIdx.x * blockDim.x + threadIdx.x;
    if (idx >= NB * NR) return;
    int r = idx % NR;
    size_t base = (size_t)idx * 8;
    const size_t UP = (size_t)NB * 9216;
    float e[8];
    float sn = 0.f;
#pragma unroll
    for (int j = 0; j < 8; j++) {
        int oc = (r * 8 + j) / 36;
        float v = g_upart[base + j] + g_upart[UP + base + j]
                + g_upart[2 * UP + base + j] + g_upart[3 * UP + base + j]
                + __ldg(pb + oc);
        e[j] = v;
        sn = fmaf(v, v, sn);
    }
    float f = sqrtf(sn) / (1.0f + sn);
    float4 o0 = make_float4(e[0] * f, e[1] * f, e[2] * f, e[3] * f);
    float4 o1 = make_float4(e[4] * f, e[5] * f, e[6] * f, e[7] * f);
    float4* o = (float4*)(g_u + base);
    o[0] = o0; o[1] = o1;
}

__global__ void __launch_bounds__(160) k_uhat(const float* __restrict__ W) {
    __shared__ float sWT[1280];
    int r = blockIdx.x, t = threadIdx.x;
    for (int j = t; j < 1280; j += 160)
        sWT[j] = W[(size_t)r * 1280 + (j % 160) * 8 + j / 160];
    __syncthreads();
    float w0 = sWT[t], w1 = sWT[160+t], w2 = sWT[320+t], w3 = sWT[480+t];
    float w4 = sWT[640+t], w5 = sWT[800+t], w6 = sWT[960+t], w7 = sWT[1120+t];
#pragma unroll 4
    for (int b = 0; b < NB; b++) {
        const float4* up = (const float4*)(g_u + (size_t)b * 9216 + r * 8);
        float4 ua = up[0], ub = up[1];
        G_UHAT[((size_t)b * NR + r) * 160 + t] =
            ua.x*w0 + ua.y*w1 + ua.z*w2 + ua.w*w3 + ub.x*w4 + ub.y*w5 + ub.z*w6 + ub.w*w7;
    }
}

__global__ void k_softmax() {
    __shared__ float sred[128];
    int c = blockIdx.x, t = threadIdx.x;
    float mx = -1e30f;
    for (int r = t; r < NR; r += 128) mx = fmaxf(mx, g_bij[r * NC2 + c]);
    sred[t] = mx; __syncthreads();
    for (int st = 64; st >= 1; st >>= 1) { if (t < st) sred[t] = fmaxf(sred[t], sred[t + st]); __syncthreads(); }
    mx = sred[0]; __syncthreads();
    float sm = 0.f;
    for (int r = t; r < NR; r += 128) sm += expf(g_bij[r * NC2 + c] - mx);
    sred[t] = sm; __syncthreads();
    for (int st = 64; st >= 1; st >>= 1) { if (t < st) sred[t] += sred[t + st]; __syncthreads(); }
    float inv = 1.0f / sred[0];
    for (int r = t; r < NR; r += 128)
        g_cij[r * NC2 + c] = expf(g_bij[r * NC2 + c] - mx) * inv;
}

__global__ void __launch_bounds__(256) k_sj(float* out, int it) {
    __shared__ float4 sred[64][4];
    int b = blockIdx.x, c = blockIdx.y, t = threadIdx.x;
    int og = t & 3, rg = t >> 2;
    float4 acc = make_float4(0.f, 0.f, 0.f, 0.f);
    if (it == 0) {
        for (int r = rg; r < NR; r += 64) {
            float4 u4 = g_uhat4[(((size_t)b * NR + r) * NC2 + c) * 4 + og];
            acc.x += u4.x; acc.y += u4.y; acc.z += u4.z; acc.w += u4.w;
        }
        const float s = 1.0f / NR;
        acc.x *= s; acc.y *= s; acc.z *= s; acc.w *= s;
    } else {
        for (int r = rg; r < NR; r += 64) {
            float cij = __ldg(g_cij + r * NC2 + c);
            float4 u4 = g_uhat4[(((size_t)b * NR + r) * NC2 + c) * 4 + og];
            acc.x = fmaf(cij, u4.x, acc.x); acc.y = fmaf(cij, u4.y, acc.y);
            acc.z = fmaf(cij, u4.z, acc.z); acc.w = fmaf(cij, u4.w, acc.w);
        }
    }
    sred[rg][og] = acc;
    __syncthreads();
    for (int st = 32; st >= 1; st >>= 1) {
        if (rg < st) {
            float4 o4 = sred[rg + st][og];
            acc.x += o4.x; acc.y += o4.y; acc.z += o4.z; acc.w += o4.w;
            sred[rg][og] = acc;
        }
        __syncthreads();
    }
    if (rg == 0) {
        float4 v;
        v.x = acc.x * fabsf(acc.x) / (1.f + acc.x * acc.x);
        v.y = acc.y * fabsf(acc.y) / (1.f + acc.y * acc.y);
        v.z = acc.z * fabsf(acc.z) / (1.f + acc.z * acc.z);
        v.w = acc.w * fabsf(acc.w) / (1.f + acc.w * acc.w);
        g_v4[(b * NC2 + c) * 4 + og] = v;
        if (out) ((float4*)out)[(b * NC2 + c) * 4 + og] = v;
    }
}

__global__ void __launch_bounds__(256) k_aij(int first) {
    __shared__ float sred[256];
    int r = blockIdx.x, c = blockIdx.y, t = threadIdx.x;
    int og = t & 3, bg = t >> 2;
    float acc = 0.f;
    for (int b = bg; b < NB; b += 64) {
        float4 u4 = g_uhat4[(((size_t)b * NR + r) * NC2 + c) * 4 + og];
        float4 v4 = g_v4[(b * NC2 + c) * 4 + og];
        acc += u4.x * v4.x + u4.y * v4.y + u4.z * v4.z + u4.w * v4.w;
    }
    sred[t] = acc; __syncthreads();
    for (int st = 128; st >= 1; st >>= 1) { if (t < st) sred[t] += sred[t + st]; __syncthreads(); }
    if (t == 0) {
        float a = sred[0] * (1.0f / NB);
        if (first) g_bij[r * NC2 + c] = a;
        else g_bij[r * NC2 + c] += a;
    }
}

__global__ void __launch_bounds__(128) k_cls(const float* __restrict__ w1,
                                             const float* __restrict__ b1,
                                             const float* __restrict__ w2,
                                             const float* __restrict__ b2,
                                             float* out) {
    __shared__ float sfeat[160];
    __shared__ float sred[128];
    int b = blockIdx.x, k = blockIdx.y, t = threadIdx.x;
    for (int j = t; j < 160; j += 128) sfeat[j] = G_V[b * 160 + j];
    __syncthreads();
    float val = 0.f;
    if (t < 100) {
        float acc = __ldg(b1 + k * 100 + t);
        const float* wp = w1 + (size_t)k * 16000 + t;
#pragma unroll 4
        for (int f = 0; f < 160; f++) acc = fmaf(sfeat[f], wp[f * 100], acc);
        val = fmaxf(acc, 0.f) * __ldg(w2 + k * 100 + t);
    }
    sred[t] = val; __syncthreads();
    for (int st = 64; st >= 1; st >>= 1) { if (t < st) sred[t] += sred[t + st]; __syncthreads(); }
    if (t == 0)
        out[40960 + b * NC2 + k] = 1.0f / (1.0f + expf(-(sred[0] + __ldg(b2 + k))));
}

extern "C" void kernel_launch(void* const* d_in, const int* in_sizes, int n_in,
                              void* d_out, int out_size) {
    const float* data    = (const float*)d_in[0];
    const float* conv1_w = (const float*)d_in[1];
    const float* conv1_b = (const float*)d_in[2];
    const float* conv2_w = (const float*)d_in[3];
    const float* conv2_b = (const float*)d_in[4];
    const float* prim_w  = (const float*)d_in[5];
    const float* prim_b  = (const float*)d_in[6];
    const float* W       = (const float*)d_in[7];
    const float* cls_w1  = (const float*)d_in[8];
    const float* cls_b1  = (const float*)d_in[9];
    const float* cls_w2  = (const float*)d_in[10];
    const float* cls_b2  = (const float*)d_in[11];
    float* out = (float*)d_out;

    static int inited = 0;
    if (!inited) {
        cudaFuncSetAttribute(k_conv2mma, cudaFuncAttributeMaxDynamicSharedMemorySize, 2 * BUFB);
        cudaFuncSetAttribute(k_primmma, cudaFuncAttributeMaxDynamicSharedMemorySize, 2 * BUFB);
        inited = 1;
    }

    k_cvt_w2<<<288, 256>>>(conv2_w);
    k_cvt_pw<<<10368, 256>>>(prim_w);
    k_conv1pool<<<1444, 256>>>(data, conv1_w, conv1_b);
    k_conv2mma<<<dim3(13, NB), 256, 2 * BUFB>>>(conv2_b);
    k_pool2n<<<NB * 200, 256>>>();
    k_primmma<<<dim3(72, 2, 4), 256, 2 * BUFB>>>();
    k_squash<<<(NB * NR + 255) / 256, 256>>>(prim_b);
    k_uhat<<<NR, 160>>>(W);

    for (int it = 0; it < 3; it++) {
        if (it > 0) k_softmax<<<NC2, 128>>>();
        k_sj<<<dim3(NB, NC2), 256>>>(it == 2 ? out : nullptr, it);
        if (it < 2) k_aij<<<dim3(NR, NC2), 256>>>(it == 0 ? 1 : 0);
    }
    k_cls<<<dim3(NB, NC2), 128>>>(cls_w1, cls_b1, cls_w2, cls_b2, out);
}

// round 16
// speedup vs baseline: 1.4103x; 1.4103x over previous
#include <cuda_runtime.h>
#include <cuda_bf16.h>
#include <math.h>
#include <stdint.h>

#define NB 256
#define NR 1152
#define NC2 10
#define LDA 40
#define BUFB 40960
#define BUFE 20480

__device__ __forceinline__ void mma16816(float* d, unsigned a0, unsigned a1, unsigned a2, unsigned a3,
                                         unsigned b0, unsigned b1) {
    asm volatile("mma.sync.aligned.m16n8k16.row.col.f32.bf16.bf16.f32 "
        "{%0,%1,%2,%3}, {%4,%5,%6,%7}, {%8,%9}, {%0,%1,%2,%3};"
        : "+f"(d[0]), "+f"(d[1]), "+f"(d[2]), "+f"(d[3])
        : "r"(a0), "r"(a1), "r"(a2), "r"(a3), "r"(b0), "r"(b1));
}
__device__ __forceinline__ void ldsm_x4(unsigned* r, uint32_t addr) {
    asm volatile("ldmatrix.sync.aligned.m8n8.x4.shared.b16 {%0,%1,%2,%3}, [%4];"
        : "=r"(r[0]), "=r"(r[1]), "=r"(r[2]), "=r"(r[3]) : "r"(addr));
}
__device__ __forceinline__ void bfsplit(float f, __nv_bfloat16& h, __nv_bfloat16& l) {
    h = __float2bfloat16(f);
    l = __float2bfloat16(f - __bfloat162float(h));
}
__device__ __forceinline__ unsigned packhl(float f) {
    __nv_bfloat16 h, l; bfsplit(f, h, l);
    return (unsigned)__bfloat16_as_ushort(h) | ((unsigned)__bfloat16_as_ushort(l) << 16);
}
__device__ __forceinline__ void cp16(uint32_t dst, const void* src) {
    asm volatile("cp.async.ca.shared.global [%0], [%1], 16;" :: "r"(dst), "l"(src));
}

// ---- scratch ----
__device__ unsigned g_p1p[(size_t)NB * 64 * 1444];
__device__ float g_c2[(size_t)NB * 1444 * 128];
__device__ unsigned g_p2p[(size_t)NB * 128 * 400];
__device__ __nv_bfloat16 g_w2c[18 * 1024 * 8];              // conv2 W chunk-major
__device__ __nv_bfloat16 g_pwc[(size_t)2 * 324 * 1024 * 8]; // prim W chunk-major [ny][kc][i]
__device__ float g_upart[(size_t)4 * NB * 9216];
__device__ float g_u[(size_t)NB * 9216];
__device__ float4 g_uhat4[(size_t)NB * NR * NC2 * 4];
__device__ float g_bij[NR * NC2];
__device__ float g_cij[NR * NC2];
__device__ float4 g_v4[NB * NC2 * 4];
#define G_UHAT ((float*)g_uhat4)
#define G_V ((float*)g_v4)

// ---- weight repack: chunk-major, matching staging consumption order ----
__global__ void k_cvt_w2(const float* __restrict__ w2) {
    int e = blockIdx.x * blockDim.x + threadIdx.x;       // 147456
    if (e >= 18 * 1024 * 8) return;
    int j = e & 7;
    int i16 = e >> 3;
    int i = i16 & 1023, kc = i16 >> 10;
    int half = i >> 9, n = (i >> 2) & 127, seg = i & 3;
    int k = kc * 32 + seg * 8 + j;
    __nv_bfloat16 h, l; bfsplit(w2[n * 576 + k], h, l);
    g_w2c[e] = half ? l : h;
}
__global__ void k_cvt_pw(const float* __restrict__ pw) {
    size_t e = (size_t)blockIdx.x * blockDim.x + threadIdx.x;  // 5308416
    int j = (int)(e & 7);
    size_t i16 = e >> 3;
    int i = (int)(i16 & 1023);
    int kc = (int)((i16 >> 10) % 324);
    int ny = (int)(i16 / (1024 * 324));
    int half = i >> 9, n = (i >> 2) & 127, seg = i & 3;
    int oc = ny * 128 + n;
    int k = kc * 32 + seg * 8 + j;
    __nv_bfloat16 h, l; bfsplit(pw[(size_t)oc * 10368 + k], h, l);
    g_pwc[e] = half ? l : h;
}

// ---- conv1+relu+pool ----
__global__ void __launch_bounds__(256) k_conv1pool(const float* __restrict__ data,
                                                   const float* __restrict__ w1,
                                                   const float* __restrict__ b1) {
    __shared__ float sw[1728];
    __shared__ float sb[64];
    int tid = threadIdx.x;
    for (int i = tid; i < 1728; i += 256) sw[i] = w1[i];
    if (tid < 64) sb[tid] = b1[tid];
    __syncthreads();

    int idx = blockIdx.x * blockDim.x + tid;
    int p = idx % 1444, b = idx / 1444;
    int pj = p / 38, pi = p % 38;
    int y0 = 2 * pj - 1, x0 = 2 * pi - 1;
    float iv[3][4][4];
#pragma unroll
    for (int ic = 0; ic < 3; ic++)
#pragma unroll
        for (int dy = 0; dy < 4; dy++) {
            int yy = y0 + dy;
#pragma unroll
            for (int dx = 0; dx < 4; dx++) {
                int xx = x0 + dx;
                float v = 0.f;
                if (yy >= 0 && yy < 76 && xx >= 0 && xx < 76)
                    v = data[((size_t)(b * 3 + ic) * 76 + yy) * 76 + xx];
                iv[ic][dy][dx] = v;
            }
        }
    bool rv0 = (y0 >= 0), rv1 = (y0 + 1 <= 73), cv0 = (x0 >= 0), cv1 = (x0 + 1 <= 73);
    size_t obase = (size_t)b * 64 * 1444 + (size_t)pj * 38 + pi;
#pragma unroll 1
    for (int oc = 0; oc < 64; oc += 2) {
        const float* wa = sw + oc * 27;
        const float* wb = wa + 27;
        float a00 = 0.f, a01 = 0.f, a10 = 0.f, a11 = 0.f;
        float c00 = 0.f, c01 = 0.f, c10 = 0.f, c11 = 0.f;
#pragma unroll
        for (int k = 0; k < 27; k++) {
            int ic = k / 9, r = (k / 3) % 3, c2 = k % 3;
            float v00 = iv[ic][r][c2], v01 = iv[ic][r][c2 + 1];
            float v10 = iv[ic][r + 1][c2], v11 = iv[ic][r + 1][c2 + 1];
            float wA = wa[k], wB = wb[k];
            a00 = fmaf(v00, wA, a00); a01 = fmaf(v01, wA, a01);
            a10 = fmaf(v10, wA, a10); a11 = fmaf(v11, wA, a11);
            c00 = fmaf(v00, wB, c00); c01 = fmaf(v01, wB, c01);
            c10 = fmaf(v10, wB, c10); c11 = fmaf(v11, wB, c11);
        }
        float boA = sb[oc], boB = sb[oc + 1];
        float mA = 0.f, mB = 0.f;
        if (rv0 && cv0) { mA = fmaxf(mA, a00 + boA); mB = fmaxf(mB, c00 + boB); }
        if (rv0 && cv1) { mA = fmaxf(mA, a01 + boA); mB = fmaxf(mB, c01 + boB); }
        if (rv1 && cv0) { mA = fmaxf(mA, a10 + boA); mB = fmaxf(mB, c10 + boB); }
        if (rv1 && cv1) { mA = fmaxf(mA, a11 + boA); mB = fmaxf(mB, c11 + boB); }
        g_p1p[obase + (size_t)oc * 1444] = packhl(mA);
        g_p1p[obase + (size_t)(oc + 1) * 1444] = packhl(mB);
    }
}

// ---- B staging: fully coalesced cp.async from chunk-major weights ----
__device__ __forceinline__ void stageB_cp(uint32_t dstb, const __nv_bfloat16* __restrict__ srcC,
                                          int kc, int tid) {
    const __nv_bfloat16* src = srcC + ((size_t)kc * 1024 + tid * 4) * 8;
#pragma unroll
    for (int q = 0; q < 4; q++) {
        int i = tid * 4 + q;
        int half = i >> 9, n = (i >> 2) & 127, seg = i & 3;
        uint32_t dst = dstb + (half ? 30720 : 20480) + ((unsigned)n * LDA + seg * 8) * 2;
        cp16(dst, src + q * 8);
    }
    asm volatile("cp.async.commit_group;" ::: "memory");
}
__device__ __forceinline__ void cp_wait() {
    asm volatile("cp.async.wait_group 0;" ::: "memory");
}

// ---- store A regs -> smem (perm + STS.128) ----
__device__ __forceinline__ void storeA(__nv_bfloat16* dst, const unsigned* p, int mloc, int ubase) {
    char* db = (char*)dst;
#pragma unroll
    for (int uu = 0; uu < 2; uu++) {
        int u = ubase + uu;
        unsigned hw[4], lw[4];
#pragma unroll
        for (int jj = 0; jj < 4; jj++) {
            unsigned p0 = p[uu * 8 + jj * 2], p1 = p[uu * 8 + jj * 2 + 1];
            hw[jj] = __byte_perm(p0, p1, 0x5410);
            lw[jj] = __byte_perm(p0, p1, 0x7632);
        }
        *(uint4*)(db + mloc * 80 + u * 16) = make_uint4(hw[0], hw[1], hw[2], hw[3]);
        *(uint4*)(db + 10240 + mloc * 80 + u * 16) = make_uint4(lw[0], lw[1], lw[2], lw[3]);
    }
}

// ---- gemm: warp tile M=32 x N=64 ----
__device__ __forceinline__ void gemm_chunk(float acc[16][4], uint32_t aH, uint32_t aL,
                                           uint32_t bH, uint32_t bL) {
#pragma unroll
    for (int ks = 0; ks < 2; ks++) {
        unsigned Ah[2][4], Al[2][4];
        ldsm_x4(Ah[0], aH + ks * 32);
        ldsm_x4(Ah[1], aH + 16 * LDA * 2 + ks * 32);
        ldsm_x4(Al[0], aL + ks * 32);
        ldsm_x4(Al[1], aL + 16 * LDA * 2 + ks * 32);
#pragma unroll
        for (int j = 0; j < 4; j++) {
            unsigned Bh[4], Bl[4];
            uint32_t bo = (uint32_t)j * (16 * LDA * 2) + ks * 32;
            ldsm_x4(Bh, bH + bo);
            ldsm_x4(Bl, bL + bo);
#pragma unroll
            for (int mt = 0; mt < 2; mt++) {
                int t0 = mt * 8 + j * 2;
                mma16816(acc[t0],     Ah[mt][0], Ah[mt][1], Ah[mt][2], Ah[mt][3], Bh[0], Bh[1]);
                mma16816(acc[t0],     Al[mt][0], Al[mt][1], Al[mt][2], Al[mt][3], Bh[0], Bh[1]);
                mma16816(acc[t0],     Ah[mt][0], Ah[mt][1], Ah[mt][2], Ah[mt][3], Bl[0], Bl[1]);
                mma16816(acc[t0 + 1], Ah[mt][0], Ah[mt][1], Ah[mt][2], Ah[mt][3], Bh[2], Bh[3]);
                mma16816(acc[t0 + 1], Al[mt][0], Al[mt][1], Al[mt][2], Al[mt][3], Bh[2], Bh[3]);
                mma16816(acc[t0 + 1], Ah[mt][0], Ah[mt][1], Ah[mt][2], Ah[mt][3], Bl[2], Bl[3]);
            }
        }
    }
}

// ---- conv2: synchronous A gather, coalesced B cp.async, 2 blocks/SM ----
__global__ void __launch_bounds__(256, 2) k_conv2mma(const float* __restrict__ b2) {
    extern __shared__ __nv_bfloat16 sm[];
    int tid = threadIdx.x;
    int w = tid >> 5, lane = tid & 31;
    int g = lane >> 2, tg = lane & 3;
    int wm = w & 3, wn = w >> 2;
    int bb = blockIdx.y, strip = blockIdx.x;

    uint32_t smb = (uint32_t)__cvta_generic_to_shared(sm);
    uint32_t aoff = ((unsigned)(wm * 32 + (lane & 15)) * LDA + ((lane & 16) ? 8 : 0)) * 2;
    uint32_t boff = ((unsigned)(wn * 64 + (lane & 7) + ((lane & 16) ? 8 : 0)) * LDA + ((lane & 8) ? 8 : 0)) * 2;

    float acc[16][4];
#pragma unroll
    for (int n = 0; n < 16; n++)
#pragma unroll
        for (int q = 0; q < 4; q++) acc[n][q] = 0.f;

    int mloc = tid & 127;
    int ubase = (tid >> 7) * 2;
    int pA = strip * 128 + mloc;
    int yA = pA / 38, xA = pA % 38;
    bool pvA = pA < 1444;
    const unsigned* srcp = g_p1p + (size_t)bb * 64 * 1444;

    auto stageA = [&](__nv_bfloat16* dst, int kc) {
        char* db = (char*)dst;
#pragma unroll
        for (int uu = 0; uu < 2; uu++) {
            int u = ubase + uu;
            int k = kc * 32 + u * 8;
            int ic = k / 9, r = k - ic * 9;
            int ky = r / 3, kx = r - ky * 3;
            unsigned hw[4], lw[4];
#pragma unroll
            for (int jj = 0; jj < 4; jj++) {
                unsigned p0 = 0, p1 = 0;
                {
                    int yy = yA + ky - 1, xx = xA + kx - 1;
                    if (pvA && yy >= 0 && yy < 38 && xx >= 0 && xx < 38)
                        p0 = srcp[ic * 1444 + yy * 38 + xx];
                    if (++kx == 3) { kx = 0; if (++ky == 3) { ky = 0; ic++; } }
                }
                {
                    int yy = yA + ky - 1, xx = xA + kx - 1;
                    if (pvA && yy >= 0 && yy < 38 && xx >= 0 && xx < 38)
                        p1 = srcp[ic * 1444 + yy * 38 + xx];
                    if (++kx == 3) { kx = 0; if (++ky == 3) { ky = 0; ic++; } }
                }
                hw[jj] = __byte_perm(p0, p1, 0x5410);
                lw[jj] = __byte_perm(p0, p1, 0x7632);
            }
            *(uint4*)(db + mloc * 80 + u * 16) = make_uint4(hw[0], hw[1], hw[2], hw[3]);
            *(uint4*)(db + 10240 + mloc * 80 + u * 16) = make_uint4(lw[0], lw[1], lw[2], lw[3]);
        }
    };

    stageA(sm, 0);
    stageB_cp(smb, g_w2c, 0, tid);
    cp_wait();
    __syncthreads();

#pragma unroll 1
    for (int kc = 0; kc < 18; kc++) {
        int par = kc & 1, nxt = kc + 1;
        if (nxt < 18) {
            stageA(sm + (nxt & 1) * BUFE, nxt);
            stageB_cp(smb + (nxt & 1) * BUFB, g_w2c, nxt, tid);
        }
        uint32_t base = smb + par * BUFB;
        gemm_chunk(acc, base + aoff, base + 10240 + aoff,
                        base + 20480 + boff, base + 30720 + boff);
        cp_wait();
        __syncthreads();
    }

#pragma unroll
    for (int mt = 0; mt < 2; mt++) {
        int p0 = strip * 128 + wm * 32 + mt * 16 + g;
        int p1 = p0 + 8;
#pragma unroll
        for (int j = 0; j < 4; j++)
#pragma unroll
            for (int h = 0; h < 2; h++) {
                int t = mt * 8 + j * 2 + h;
                int col = wn * 64 + j * 16 + h * 8 + tg * 2;
                float bc0 = __ldg(b2 + col), bc1 = __ldg(b2 + col + 1);
                if (p0 < 1444) {
                    float2 o; o.x = fmaxf(acc[t][0] + bc0, 0.f); o.y = fmaxf(acc[t][1] + bc1, 0.f);
                    *(float2*)(g_c2 + ((size_t)bb * 1444 + p0) * 128 + col) = o;
                }
                if (p1 < 1444) {
                    float2 o; o.x = fmaxf(acc[t][2] + bc0, 0.f); o.y = fmaxf(acc[t][3] + bc1, 0.f);
                    *(float2*)(g_c2 + ((size_t)bb * 1444 + p1) * 128 + col) = o;
                }
            }
    }
}

// ---- maxpool -> channel-major packed ----
__global__ void __launch_bounds__(256) k_pool2n() {
    __shared__ float s[16 * 129];
    int b = blockIdx.y, t0 = blockIdx.x;
    int tid = threadIdx.x;
    for (int i = tid; i < 2048; i += 256) {
        int p2l = i >> 7, oc = i & 127;
        int p2 = t0 * 16 + p2l;
        int pj = p2 / 20, pi = p2 % 20;
        int y0 = 2 * pj - 1, x0 = 2 * pi - 1;
        float m = 0.f;
#pragma unroll
        for (int dy = 0; dy < 2; dy++) {
            int y = y0 + dy; if (y < 0 || y > 37) continue;
#pragma unroll
            for (int dx = 0; dx < 2; dx++) {
                int x = x0 + dx; if (x < 0 || x > 37) continue;
                m = fmaxf(m, g_c2[((size_t)b * 1444 + y * 38 + x) * 128 + oc]);
            }
        }
        s[p2l * 129 + oc] = m;
    }
    __syncthreads();
    for (int i = tid; i < 2048; i += 256) {
        int oc = i >> 4, p2l = i & 15;
        g_p2p[((size_t)(b * 128 + oc)) * 400 + t0 * 16 + p2l] = packhl(s[p2l * 129 + oc]);
    }
}

// ---- PrimaryCaps: K-split x4, 2 blocks/SM ----
__global__ void __launch_bounds__(256, 2) k_primmma() {
    extern __shared__ __nv_bfloat16 sm[];
    int tid = threadIdx.x;
    int w = tid >> 5, lane = tid & 31;
    int g = lane >> 2, tg = lane & 3;
    int wm = w & 3, wn = w >> 2;
    int mb = blockIdx.x, ny = blockIdx.y, zz = blockIdx.z;

    uint32_t smb = (uint32_t)__cvta_generic_to_shared(sm);
    uint32_t aoff = ((unsigned)(wm * 32 + (lane & 15)) * LDA + ((lane & 16) ? 8 : 0)) * 2;
    uint32_t boff = ((unsigned)(wn * 64 + (lane & 7) + ((lane & 16) ? 8 : 0)) * LDA + ((lane & 8) ? 8 : 0)) * 2;

    float acc[16][4];
#pragma unroll
    for (int n = 0; n < 16; n++)
#pragma unroll
        for (int q = 0; q < 4; q++) acc[n][q] = 0.f;

    int mloc = tid & 127;
    int ubase = (tid >> 7) * 2;
    int mA = mb * 128 + mloc;
    int bA = mA / 36, posA = mA % 36;
    int sjA = posA / 6, siA = posA % 6;
    const unsigned* p2p = g_p2p + (size_t)bA * 51200;
    const __nv_bfloat16* pwc = g_pwc + (size_t)ny * 324 * 1024 * 8;

    auto stageA = [&](__nv_bfloat16* dst, int kc) {
        char* db = (char*)dst;
#pragma unroll
        for (int uu = 0; uu < 2; uu++) {
            int u = ubase + uu;
            int k = kc * 32 + u * 8;
            int ic = k / 81, r = k - ic * 81;
            int ky = r / 9, kx = r - ky * 9;
            int off = ic * 400 + (2 * sjA + ky) * 20 + 2 * siA + kx;
            unsigned hw[4], lw[4];
#pragma unroll
            for (int jj = 0; jj < 4; jj++) {
                unsigned p0 = p2p[off];
                if (++kx == 9) { kx = 0; if (++ky == 9) { ky = 0; off += 232; } else off += 12; }
                else off++;
                unsigned p1 = p2p[off];
                if (++kx == 9) { kx = 0; if (++ky == 9) { ky = 0; off += 232; } else off += 12; }
                else off++;
                hw[jj] = __byte_perm(p0, p1, 0x5410);
                lw[jj] = __byte_perm(p0, p1, 0x7632);
            }
            *(uint4*)(db + mloc * 80 + u * 16) = make_uint4(hw[0], hw[1], hw[2], hw[3]);
            *(uint4*)(db + 10240 + mloc * 80 + u * 16) = make_uint4(lw[0], lw[1], lw[2], lw[3]);
        }
    };

    int kc0 = zz * 81, kc1 = kc0 + 81;
    stageA(sm, kc0);
    stageB_cp(smb, pwc, kc0, tid);
    cp_wait();
    __syncthreads();

#pragma unroll 1
    for (int kc = kc0; kc < kc1; kc++) {
        int par = (kc - kc0) & 1, nxt = kc + 1;
        if (nxt < kc1) {
            stageA(sm + ((nxt - kc0) & 1) * BUFE, nxt);
            stageB_cp(smb + ((nxt - kc0) & 1) * BUFB, pwc, nxt, tid);
        }
        uint32_t base = smb + par * BUFB;
        gemm_chunk(acc, base + aoff, base + 10240 + aoff,
                        base + 20480 + boff, base + 30720 + boff);
        cp_wait();
        __syncthreads();
    }

    float* up = g_upart + (size_t)zz * NB * 9216;
#pragma unroll
    for (int mt = 0; mt < 2; mt++) {
        int m0 = mb * 128 + wm * 32 + mt * 16 + g;
        int m1 = m0 + 8;
        int b0 = m0 / 36, pos0 = m0 % 36;
        int b1i = m1 / 36, pos1 = m1 % 36;
#pragma unroll
        for (int j = 0; j < 4; j++)
#pragma unroll
            for (int h = 0; h < 2; h++) {
                int t = mt * 8 + j * 2 + h;
                int col = ny * 128 + wn * 64 + j * 16 + h * 8 + tg * 2;
                up[(size_t)b0 * 9216 + (size_t)col * 36 + pos0] = acc[t][0];
                up[(size_t)b0 * 9216 + (size_t)(col + 1) * 36 + pos0] = acc[t][1];
                up[(size_t)b1i * 9216 + (size_t)col * 36 + pos1] = acc[t][2];
                up[(size_t)b1i * 9216 + (size_t)(col + 1) * 36 + pos1] = acc[t][3];
            }
    }
}

// ---- squash: sum 4 K-slices + bias ----
__global__ void k_squash(const float* __restrict__ pb) {
    int idx = blockIdx.x * blockDim.x + threadIdx.x;
    if (idx >= NB * NR) return;
    int r = idx % NR;
    size_t base = (size_t)idx * 8;
    const size_t UP = (size_t)NB * 9216;
    float e[8];
    float sn = 0.f;
#pragma unroll
    for (int j = 0; j < 8; j++) {
        int oc = (r * 8 + j) / 36;
        float v = g_upart[base + j] + g_upart[UP + base + j]
                + g_upart[2 * UP + base + j] + g_upart[3 * UP + base + j]
                + __ldg(pb + oc);
        e[j] = v;
        sn = fmaf(v, v, sn);
    }
    float f = sqrtf(sn) / (1.0f + sn);
    float4 o0 = make_float4(e[0] * f, e[1] * f, e[2] * f, e[3] * f);
    float4 o1 = make_float4(e[4] * f, e[5] * f, e[6] * f, e[7] * f);
    float4* o = (float4*)(g_u + base);
    o[0] = o0; o[1] = o1;
}

__global__ void __launch_bounds__(160) k_uhat(const float* __restrict__ W) {
    __shared__ float sWT[1280];
    int r = blockIdx.x, t = threadIdx.x;
    for (int j = t; j < 1280; j += 160)
        sWT[j] = W[(size_t)r * 1280 + (j % 160) * 8 + j / 160];
    __syncthreads();
    float w0 = sWT[t], w1 = sWT[160+t], w2 = sWT[320+t], w3 = sWT[480+t];
    float w4 = sWT[640+t], w5 = sWT[800+t], w6 = sWT[960+t], w7 = sWT[1120+t];
#pragma unroll 4
    for (int b = 0; b < NB; b++) {
        const float4* up = (const float4*)(g_u + (size_t)b * 9216 + r * 8);
        float4 ua = up[0], ub = up[1];
        G_UHAT[((size_t)b * NR + r) * 160 + t] =
            ua.x*w0 + ua.y*w1 + ua.z*w2 + ua.w*w3 + ub.x*w4 + ub.y*w5 + ub.z*w6 + ub.w*w7;
    }
}

__global__ void k_softmax() {
    __shared__ float sred[128];
    int c = blockIdx.x, t = threadIdx.x;
    float mx = -1e30f;
    for (int r = t; r < NR; r += 128) mx = fmaxf(mx, g_bij[r * NC2 + c]);
    sred[t] = mx; __syncthreads();
    for (int st = 64; st >= 1; st >>= 1) { if (t < st) sred[t] = fmaxf(sred[t], sred[t + st]); __syncthreads(); }
    mx = sred[0]; __syncthreads();
    float sm = 0.f;
    for (int r = t; r < NR; r += 128) sm += expf(g_bij[r * NC2 + c] - mx);
    sred[t] = sm; __syncthreads();
    for (int st = 64; st >= 1; st >>= 1) { if (t < st) sred[t] += sred[t + st]; __syncthreads(); }
    float inv = 1.0f / sred[0];
    for (int r = t; r < NR; r += 128)
        g_cij[r * NC2 + c] = expf(g_bij[r * NC2 + c] - mx) * inv;
}

__global__ void __launch_bounds__(256) k_sj(float* out, int it) {
    __shared__ float4 sred[64][4];
    int b = blockIdx.x, c = blockIdx.y, t = threadIdx.x;
    int og = t & 3, rg = t >> 2;
    float4 acc = make_float4(0.f, 0.f, 0.f, 0.f);
    if (it == 0) {
        for (int r = rg; r < NR; r += 64) {
            float4 u4 = g_uhat4[(((size_t)b * NR + r) * NC2 + c) * 4 + og];
            acc.x += u4.x; acc.y += u4.y; acc.z += u4.z; acc.w += u4.w;
        }
        const float s = 1.0f / NR;
        acc.x *= s; acc.y *= s; acc.z *= s; acc.w *= s;
    } else {
        for (int r = rg; r < NR; r += 64) {
            float cij = __ldg(g_cij + r * NC2 + c);
            float4 u4 = g_uhat4[(((size_t)b * NR + r) * NC2 + c) * 4 + og];
            acc.x = fmaf(cij, u4.x, acc.x); acc.y = fmaf(cij, u4.y, acc.y);
            acc.z = fmaf(cij, u4.z, acc.z); acc.w = fmaf(cij, u4.w, acc.w);
        }
    }
    sred[rg][og] = acc;
    __syncthreads();
    for (int st = 32; st >= 1; st >>= 1) {
        if (rg < st) {
            float4 o4 = sred[rg + st][og];
            acc.x += o4.x; acc.y += o4.y; acc.z += o4.z; acc.w += o4.w;
            sred[rg][og] = acc;
        }
        __syncthreads();
    }
    if (rg == 0) {
        float4 v;
        v.x = acc.x * fabsf(acc.x) / (1.f + acc.x * acc.x);
        v.y = acc.y * fabsf(acc.y) / (1.f + acc.y * acc.y);
        v.z = acc.z * fabsf(acc.z) / (1.f + acc.z * acc.z);
        v.w = acc.w * fabsf(acc.w) / (1.f + acc.w * acc.w);
        g_v4[(b * NC2 + c) * 4 + og] = v;
        if (out) ((float4*)out)[(b * NC2 + c) * 4 + og] = v;
    }
}

__global__ void __launch_bounds__(256) k_aij(int first) {
    __shared__ float sred[256];
    int r = blockIdx.x, c = blockIdx.y, t = threadIdx.x;
    int og = t & 3, bg = t >> 2;
    float acc = 0.f;
    for (int b = bg; b < NB; b += 64) {
        float4 u4 = g_uhat4[(((size_t)b * NR + r) * NC2 + c) * 4 + og];
        float4 v4 = g_v4[(b * NC2 + c) * 4 + og];
        acc += u4.x * v4.x + u4.y * v4.y + u4.z * v4.z + u4.w * v4.w;
    }
    sred[t] = acc; __syncthreads();
    for (int st = 128; st >= 1; st >>= 1) { if (t < st) sred[t] += sred[t + st]; __syncthreads(); }
    if (t == 0) {
        float a = sred[0] * (1.0f / NB);
        if (first) g_bij[r * NC2 + c] = a;
        else g_bij[r * NC2 + c] += a;
    }
}

__global__ void __launch_bounds__(128) k_cls(const float* __restrict__ w1,
                                             const float* __restrict__ b1,
                                             const float* __restrict__ w2,
                                             const float* __restrict__ b2,
                                             float* out) {
    __shared__ float sfeat[160];
    __shared__ float sred[128];
    int b = blockIdx.x, k = blockIdx.y, t = threadIdx.x;
    for (int j = t; j < 160; j += 128) sfeat[j] = G_V[b * 160 + j];
    __syncthreads();
    float val = 0.f;
    if (t < 100) {
        float acc = __ldg(b1 + k * 100 + t);
        const float* wp = w1 + (size_t)k * 16000 + t;
#pragma unroll 4
        for (int f = 0; f < 160; f++) acc = fmaf(sfeat[f], wp[f * 100], acc);
        val = fmaxf(acc, 0.f) * __ldg(w2 + k * 100 + t);
    }
    sred[t] = val; __syncthreads();
    for (int st = 64; st >= 1; st >>= 1) { if (t < st) sred[t] += sred[t + st]; __syncthreads(); }
    if (t == 0)
        out[40960 + b * NC2 + k] = 1.0f / (1.0f + expf(-(sred[0] + __ldg(b2 + k))));
}

extern "C" void kernel_launch(void* const* d_in, const int* in_sizes, int n_in,
                              void* d_out, int out_size) {
    const float* data    = (const float*)d_in[0];
    const float* conv1_w = (const float*)d_in[1];
    const float* conv1_b = (const float*)d_in[2];
    const float* conv2_w = (const float*)d_in[3];
    const float* conv2_b = (const float*)d_in[4];
    const float* prim_w  = (const float*)d_in[5];
    const float* prim_b  = (const float*)d_in[6];
    const float* W       = (const float*)d_in[7];
    const float* cls_w1  = (const float*)d_in[8];
    const float* cls_b1  = (const float*)d_in[9];
    const float* cls_w2  = (const float*)d_in[10];
    const float* cls_b2  = (const float*)d_in[11];
    float* out = (float*)d_out;

    static int inited = 0;
    if (!inited) {
        cudaFuncSetAttribute(k_conv2mma, cudaFuncAttributeMaxDynamicSharedMemorySize, 2 * BUFB);
        cudaFuncSetAttribute(k_primmma, cudaFuncAttributeMaxDynamicSharedMemorySize, 2 * BUFB);
        inited = 1;
    }

    k_cvt_w2<<<576, 256>>>(conv2_w);
    k_cvt_pw<<<20736, 256>>>(prim_w);
    k_conv1pool<<<1444, 256>>>(data, conv1_w, conv1_b);
    k_conv2mma<<<dim3(12, NB), 256, 2 * BUFB>>>(conv2_b);
    k_pool2n<<<dim3(25, NB), 256>>>();
    k_primmma<<<dim3(72, 2, 4), 256, 2 * BUFB>>>();
    k_squash<<<(NB * NR + 255) / 256, 256>>>(prim_b);
    k_uhat<<<NR, 160>>>(W);

    for (int it = 0; it < 3; it++) {
        if (it > 0) k_softmax<<<NC2, 128>>>();
        k_sj<<<dim3(NB, NC2), 256>>>(it == 2 ? out : nullptr, it);
        if (it < 2) k_aij<<<dim3(NR, NC2), 256>>>(it == 0 ? 1 : 0);
    }
    k_cls<<<dim3(NB, NC2), 128>>>(cls_w1, cls_b1, cls_w2, cls_b2, out);
}

// round 17
// speedup vs baseline: 1.4218x; 1.0082x over previous
#include <cuda_runtime.h>
#include <cuda_bf16.h>
#include <math.h>
#include <stdint.h>

#define NB 256
#define NR 1152
#define NC2 10
#define LDA 40
#define BUFB 40960
#define BUFE 20480

__device__ __forceinline__ void mma16816(float* d, unsigned a0, unsigned a1, unsigned a2, unsigned a3,
                                         unsigned b0, unsigned b1) {
    asm volatile("mma.sync.aligned.m16n8k16.row.col.f32.bf16.bf16.f32 "
        "{%0,%1,%2,%3}, {%4,%5,%6,%7}, {%8,%9}, {%0,%1,%2,%3};"
        : "+f"(d[0]), "+f"(d[1]), "+f"(d[2]), "+f"(d[3])
        : "r"(a0), "r"(a1), "r"(a2), "r"(a3), "r"(b0), "r"(b1));
}
__device__ __forceinline__ void ldsm_x4(unsigned* r, uint32_t addr) {
    asm volatile("ldmatrix.sync.aligned.m8n8.x4.shared.b16 {%0,%1,%2,%3}, [%4];"
        : "=r"(r[0]), "=r"(r[1]), "=r"(r[2]), "=r"(r[3]) : "r"(addr));
}
__device__ __forceinline__ void bfsplit(float f, __nv_bfloat16& h, __nv_bfloat16& l) {
    h = __float2bfloat16(f);
    l = __float2bfloat16(f - __bfloat162float(h));
}
__device__ __forceinline__ unsigned packhl(float f) {
    __nv_bfloat16 h, l; bfsplit(f, h, l);
    return (unsigned)__bfloat16_as_ushort(h) | ((unsigned)__bfloat16_as_ushort(l) << 16);
}
__device__ __forceinline__ void cp16(uint32_t dst, const void* src) {
    asm volatile("cp.async.ca.shared.global [%0], [%1], 16;" :: "r"(dst), "l"(src));
}

// ---- scratch ----
__device__ unsigned g_p1p[(size_t)NB * 64 * 1444];
__device__ float g_c2[(size_t)NB * 1444 * 128];
__device__ unsigned g_p2p[(size_t)NB * 128 * 400];
__device__ __nv_bfloat16 g_w2c[18 * 1024 * 8];
__device__ __nv_bfloat16 g_pwc[(size_t)2 * 324 * 1024 * 8];
__device__ int g_t2[576];             // conv2 im2col table: (off<<4)|sel
__device__ int g_tp[10368];           // prim im2col table: off
__device__ float g_upart[(size_t)4 * NB * 9216];
__device__ float g_u[(size_t)NB * 9216];
__device__ float4 g_uhat4[(size_t)NB * NR * NC2 * 4];
__device__ float g_bij[NR * NC2];
__device__ float g_cij[NR * NC2];
__device__ float4 g_v4[NB * NC2 * 4];
#define G_UHAT ((float*)g_uhat4)
#define G_V ((float*)g_v4)

// ---- im2col offset tables ----
__global__ void k_tabs() {
    int k = blockIdx.x * blockDim.x + threadIdx.x;
    if (k < 576) {
        int ic = k / 9, r = k - ic * 9, ky = r / 3, kx = r - ky * 3;
        int off = ic * 1444 + (ky - 1) * 38 + (kx - 1);
        g_t2[k] = (off << 4) | r;
    }
    if (k < 10368) {
        int ic = k / 81, r = k - ic * 81, ky = r / 9, kx = r - ky * 9;
        g_tp[k] = ic * 400 + ky * 20 + kx;
    }
}

// ---- weight repack: chunk-major ----
__global__ void k_cvt_w2(const float* __restrict__ w2) {
    int e = blockIdx.x * blockDim.x + threadIdx.x;
    if (e >= 18 * 1024 * 8) return;
    int j = e & 7;
    int i16 = e >> 3;
    int i = i16 & 1023, kc = i16 >> 10;
    int half = i >> 9, n = (i >> 2) & 127, seg = i & 3;
    int k = kc * 32 + seg * 8 + j;
    __nv_bfloat16 h, l; bfsplit(w2[n * 576 + k], h, l);
    g_w2c[e] = half ? l : h;
}
__global__ void k_cvt_pw(const float* __restrict__ pw) {
    size_t e = (size_t)blockIdx.x * blockDim.x + threadIdx.x;
    int j = (int)(e & 7);
    size_t i16 = e >> 3;
    int i = (int)(i16 & 1023);
    int kc = (int)((i16 >> 10) % 324);
    int ny = (int)(i16 / (1024 * 324));
    int half = i >> 9, n = (i >> 2) & 127, seg = i & 3;
    int oc = ny * 128 + n;
    int k = kc * 32 + seg * 8 + j;
    __nv_bfloat16 h, l; bfsplit(pw[(size_t)oc * 10368 + k], h, l);
    g_pwc[e] = half ? l : h;
}

// ---- conv1+relu+pool ----
__global__ void __launch_bounds__(256) k_conv1pool(const float* __restrict__ data,
                                                   const float* __restrict__ w1,
                                                   const float* __restrict__ b1) {
    __shared__ float sw[1728];
    __shared__ float sb[64];
    int tid = threadIdx.x;
    for (int i = tid; i < 1728; i += 256) sw[i] = w1[i];
    if (tid < 64) sb[tid] = b1[tid];
    __syncthreads();

    int idx = blockIdx.x * blockDim.x + tid;
    int p = idx % 1444, b = idx / 1444;
    int pj = p / 38, pi = p % 38;
    int y0 = 2 * pj - 1, x0 = 2 * pi - 1;
    float iv[3][4][4];
#pragma unroll
    for (int ic = 0; ic < 3; ic++)
#pragma unroll
        for (int dy = 0; dy < 4; dy++) {
            int yy = y0 + dy;
#pragma unroll
            for (int dx = 0; dx < 4; dx++) {
                int xx = x0 + dx;
                float v = 0.f;
                if (yy >= 0 && yy < 76 && xx >= 0 && xx < 76)
                    v = data[((size_t)(b * 3 + ic) * 76 + yy) * 76 + xx];
                iv[ic][dy][dx] = v;
            }
        }
    bool rv0 = (y0 >= 0), rv1 = (y0 + 1 <= 73), cv0 = (x0 >= 0), cv1 = (x0 + 1 <= 73);
    size_t obase = (size_t)b * 64 * 1444 + (size_t)pj * 38 + pi;
#pragma unroll 1
    for (int oc = 0; oc < 64; oc += 2) {
        const float* wa = sw + oc * 27;
        const float* wb = wa + 27;
        float a00 = 0.f, a01 = 0.f, a10 = 0.f, a11 = 0.f;
        float c00 = 0.f, c01 = 0.f, c10 = 0.f, c11 = 0.f;
#pragma unroll
        for (int k = 0; k < 27; k++) {
            int ic = k / 9, r = (k / 3) % 3, c2 = k % 3;
            float v00 = iv[ic][r][c2], v01 = iv[ic][r][c2 + 1];
            float v10 = iv[ic][r + 1][c2], v11 = iv[ic][r + 1][c2 + 1];
            float wA = wa[k], wB = wb[k];
            a00 = fmaf(v00, wA, a00); a01 = fmaf(v01, wA, a01);
            a10 = fmaf(v10, wA, a10); a11 = fmaf(v11, wA, a11);
            c00 = fmaf(v00, wB, c00); c01 = fmaf(v01, wB, c01);
            c10 = fmaf(v10, wB, c10); c11 = fmaf(v11, wB, c11);
        }
        float boA = sb[oc], boB = sb[oc + 1];
        float mA = 0.f, mB = 0.f;
        if (rv0 && cv0) { mA = fmaxf(mA, a00 + boA); mB = fmaxf(mB, c00 + boB); }
        if (rv0 && cv1) { mA = fmaxf(mA, a01 + boA); mB = fmaxf(mB, c01 + boB); }
        if (rv1 && cv0) { mA = fmaxf(mA, a10 + boA); mB = fmaxf(mB, c10 + boB); }
        if (rv1 && cv1) { mA = fmaxf(mA, a11 + boA); mB = fmaxf(mB, c11 + boB); }
        g_p1p[obase + (size_t)oc * 1444] = packhl(mA);
        g_p1p[obase + (size_t)(oc + 1) * 1444] = packhl(mB);
    }
}

// ---- B staging: coalesced cp.async from chunk-major weights ----
__device__ __forceinline__ void stageB_cp(uint32_t dstb, const __nv_bfloat16* __restrict__ srcC,
                                          int kc, int tid) {
    const __nv_bfloat16* src = srcC + ((size_t)kc * 1024 + tid * 4) * 8;
#pragma unroll
    for (int q = 0; q < 4; q++) {
        int i = tid * 4 + q;
        int half = i >> 9, n = (i >> 2) & 127, seg = i & 3;
        uint32_t dst = dstb + (half ? 30720 : 20480) + ((unsigned)n * LDA + seg * 8) * 2;
        cp16(dst, src + q * 8);
    }
    asm volatile("cp.async.commit_group;" ::: "memory");
}
__device__ __forceinline__ void cp_wait() {
    asm volatile("cp.async.wait_group 0;" ::: "memory");
}

// ---- gemm: warp tile M=32 x N=64 ----
__device__ __forceinline__ void gemm_chunk(float acc[16][4], uint32_t aH, uint32_t aL,
                                           uint32_t bH, uint32_t bL) {
#pragma unroll
    for (int ks = 0; ks < 2; ks++) {
        unsigned Ah[2][4], Al[2][4];
        ldsm_x4(Ah[0], aH + ks * 32);
        ldsm_x4(Ah[1], aH + 16 * LDA * 2 + ks * 32);
        ldsm_x4(Al[0], aL + ks * 32);
        ldsm_x4(Al[1], aL + 16 * LDA * 2 + ks * 32);
#pragma unroll
        for (int j = 0; j < 4; j++) {
            unsigned Bh[4], Bl[4];
            uint32_t bo = (uint32_t)j * (16 * LDA * 2) + ks * 32;
            ldsm_x4(Bh, bH + bo);
            ldsm_x4(Bl, bL + bo);
#pragma unroll
            for (int mt = 0; mt < 2; mt++) {
                int t0 = mt * 8 + j * 2;
                mma16816(acc[t0],     Ah[mt][0], Ah[mt][1], Ah[mt][2], Ah[mt][3], Bh[0], Bh[1]);
                mma16816(acc[t0],     Al[mt][0], Al[mt][1], Al[mt][2], Al[mt][3], Bh[0], Bh[1]);
                mma16816(acc[t0],     Ah[mt][0], Ah[mt][1], Ah[mt][2], Ah[mt][3], Bl[0], Bl[1]);
                mma16816(acc[t0 + 1], Ah[mt][0], Ah[mt][1], Ah[mt][2], Ah[mt][3], Bh[2], Bh[3]);
                mma16816(acc[t0 + 1], Al[mt][0], Al[mt][1], Al[mt][2], Al[mt][3], Bh[2], Bh[3]);
                mma16816(acc[t0 + 1], Ah[mt][0], Ah[mt][1], Ah[mt][2], Ah[mt][3], Bl[2], Bl[3]);
            }
        }
    }
}

// ---- conv2: table-driven A gather, coalesced B, 2 blocks/SM ----
__global__ void __launch_bounds__(256, 2) k_conv2mma(const float* __restrict__ b2) {
    extern __shared__ __nv_bfloat16 sm[];
    int tid = threadIdx.x;
    int w = tid >> 5, lane = tid & 31;
    int g = lane >> 2, tg = lane & 3;
    int wm = w & 3, wn = w >> 2;
    int bb = blockIdx.y, strip = blockIdx.x;

    uint32_t smb = (uint32_t)__cvta_generic_to_shared(sm);
    uint32_t aoff = ((unsigned)(wm * 32 + (lane & 15)) * LDA + ((lane & 16) ? 8 : 0)) * 2;
    uint32_t boff = ((unsigned)(wn * 64 + (lane & 7) + ((lane & 16) ? 8 : 0)) * LDA + ((lane & 8) ? 8 : 0)) * 2;

    float acc[16][4];
#pragma unroll
    for (int n = 0; n < 16; n++)
#pragma unroll
        for (int q = 0; q < 4; q++) acc[n][q] = 0.f;

    int mloc = tid & 127;
    int ubase = (tid >> 7) * 2;
    int pA = strip * 128 + mloc;
    int yA = pA / 38, xA = pA % 38;
    bool pvA = pA < 1444;
    const unsigned* srcp = g_p1p + (size_t)bb * 64 * 1444;
    int pb = yA * 38 + xA;

    unsigned m9 = 0;
    if (pvA) {
#pragma unroll
        for (int ky = 0; ky < 3; ky++) {
            bool yo = (unsigned)(yA + ky - 1) < 38u;
#pragma unroll
            for (int kx = 0; kx < 3; kx++) {
                bool xo = (unsigned)(xA + kx - 1) < 38u;
                m9 |= (unsigned)(yo && xo) << (ky * 3 + kx);
            }
        }
    }

    auto stageA = [&](__nv_bfloat16* dst, int kc) {
        char* db = (char*)dst;
#pragma unroll
        for (int uu = 0; uu < 2; uu++) {
            int u = ubase + uu;
            int kbase = kc * 32 + u * 8;
            unsigned hw[4], lw[4];
#pragma unroll
            for (int jj = 0; jj < 4; jj++) {
                int t0 = __ldg(g_t2 + kbase + jj * 2);
                int t1 = __ldg(g_t2 + kbase + jj * 2 + 1);
                unsigned p0 = ((m9 >> (t0 & 15)) & 1) ? srcp[pb + (t0 >> 4)] : 0u;
                unsigned p1 = ((m9 >> (t1 & 15)) & 1) ? srcp[pb + (t1 >> 4)] : 0u;
                hw[jj] = __byte_perm(p0, p1, 0x5410);
                lw[jj] = __byte_perm(p0, p1, 0x7632);
            }
            *(uint4*)(db + mloc * 80 + u * 16) = make_uint4(hw[0], hw[1], hw[2], hw[3]);
            *(uint4*)(db + 10240 + mloc * 80 + u * 16) = make_uint4(lw[0], lw[1], lw[2], lw[3]);
        }
    };

    stageA(sm, 0);
    stageB_cp(smb, g_w2c, 0, tid);
    cp_wait();
    __syncthreads();

#pragma unroll 1
    for (int kc = 0; kc < 18; kc++) {
        int par = kc & 1, nxt = kc + 1;
        if (nxt < 18) {
            stageA(sm + (nxt & 1) * BUFE, nxt);
            stageB_cp(smb + (nxt & 1) * BUFB, g_w2c, nxt, tid);
        }
        uint32_t base = smb + par * BUFB;
        gemm_chunk(acc, base + aoff, base + 10240 + aoff,
                        base + 20480 + boff, base + 30720 + boff);
        cp_wait();
        __syncthreads();
    }

#pragma unroll
    for (int mt = 0; mt < 2; mt++) {
        int p0 = strip * 128 + wm * 32 + mt * 16 + g;
        int p1 = p0 + 8;
#pragma unroll
        for (int j = 0; j < 4; j++)
#pragma unroll
            for (int h = 0; h < 2; h++) {
                int t = mt * 8 + j * 2 + h;
                int col = wn * 64 + j * 16 + h * 8 + tg * 2;
                float bc0 = __ldg(b2 + col), bc1 = __ldg(b2 + col + 1);
                if (p0 < 1444) {
                    float2 o; o.x = fmaxf(acc[t][0] + bc0, 0.f); o.y = fmaxf(acc[t][1] + bc1, 0.f);
                    *(float2*)(g_c2 + ((size_t)bb * 1444 + p0) * 128 + col) = o;
                }
                if (p1 < 1444) {
                    float2 o; o.x = fmaxf(acc[t][2] + bc0, 0.f); o.y = fmaxf(acc[t][3] + bc1, 0.f);
                    *(float2*)(g_c2 + ((size_t)bb * 1444 + p1) * 128 + col) = o;
                }
            }
    }
}

// ---- maxpool -> channel-major packed ----
__global__ void __launch_bounds__(256) k_pool2n() {
    __shared__ float s[16 * 129];
    int b = blockIdx.y, t0 = blockIdx.x;
    int tid = threadIdx.x;
    for (int i = tid; i < 2048; i += 256) {
        int p2l = i >> 7, oc = i & 127;
        int p2 = t0 * 16 + p2l;
        int pj = p2 / 20, pi = p2 % 20;
        int y0 = 2 * pj - 1, x0 = 2 * pi - 1;
        float m = 0.f;
#pragma unroll
        for (int dy = 0; dy < 2; dy++) {
            int y = y0 + dy; if (y < 0 || y > 37) continue;
#pragma unroll
            for (int dx = 0; dx < 2; dx++) {
                int x = x0 + dx; if (x < 0 || x > 37) continue;
                m = fmaxf(m, g_c2[((size_t)b * 1444 + y * 38 + x) * 128 + oc]);
            }
        }
        s[p2l * 129 + oc] = m;
    }
    __syncthreads();
    for (int i = tid; i < 2048; i += 256) {
        int oc = i >> 4, p2l = i & 15;
        g_p2p[((size_t)(b * 128 + oc)) * 400 + t0 * 16 + p2l] = packhl(s[p2l * 129 + oc]);
    }
}

// ---- PrimaryCaps: table-driven A gather, K-split x4 ----
__global__ void __launch_bounds__(256, 2) k_primmma() {
    extern __shared__ __nv_bfloat16 sm[];
    int tid = threadIdx.x;
    int w = tid >> 5, lane = tid & 31;
    int g = lane >> 2, tg = lane & 3;
    int wm = w & 3, wn = w >> 2;
    int mb = blockIdx.x, ny = blockIdx.y, zz = blockIdx.z;

    uint32_t smb = (uint32_t)__cvta_generic_to_shared(sm);
    uint32_t aoff = ((unsigned)(wm * 32 + (lane & 15)) * LDA + ((lane & 16) ? 8 : 0)) * 2;
    uint32_t boff = ((unsigned)(wn * 64 + (lane & 7) + ((lane & 16) ? 8 : 0)) * LDA + ((lane & 8) ? 8 : 0)) * 2;

    float acc[16][4];
#pragma unroll
    for (int n = 0; n < 16; n++)
#pragma unroll
        for (int q = 0; q < 4; q++) acc[n][q] = 0.f;

    int mloc = tid & 127;
    int ubase = (tid >> 7) * 2;
    int mA = mb * 128 + mloc;
    int bA = mA / 36, posA = mA % 36;
    int sjA = posA / 6, siA = posA % 6;
    const unsigned* p2p = g_p2p + (size_t)bA * 51200 + sjA * 40 + siA * 2;
    const __nv_bfloat16* pwc = g_pwc + (size_t)ny * 324 * 1024 * 8;

    auto stageA = [&](__nv_bfloat16* dst, int kc) {
        char* db = (char*)dst;
#pragma unroll
        for (int uu = 0; uu < 2; uu++) {
            int u = ubase + uu;
            int kbase = kc * 32 + u * 8;
            unsigned hw[4], lw[4];
#pragma unroll
            for (int jj = 0; jj < 4; jj++) {
                unsigned p0 = p2p[__ldg(g_tp + kbase + jj * 2)];
                unsigned p1 = p2p[__ldg(g_tp + kbase + jj * 2 + 1)];
                hw[jj] = __byte_perm(p0, p1, 0x5410);
                lw[jj] = __byte_perm(p0, p1, 0x7632);
            }
            *(uint4*)(db + mloc * 80 + u * 16) = make_uint4(hw[0], hw[1], hw[2], hw[3]);
            *(uint4*)(db + 10240 + mloc * 80 + u * 16) = make_uint4(lw[0], lw[1], lw[2], lw[3]);
        }
    };

    int kc0 = zz * 81, kc1 = kc0 + 81;
    stageA(sm, kc0);
    stageB_cp(smb, pwc, kc0, tid);
    cp_wait();
    __syncthreads();

#pragma unroll 1
    for (int kc = kc0; kc < kc1; kc++) {
        int par = (kc - kc0) & 1, nxt = kc + 1;
        if (nxt < kc1) {
            stageA(sm + ((nxt - kc0) & 1) * BUFE, nxt);
            stageB_cp(smb + ((nxt - kc0) & 1) * BUFB, pwc, nxt, tid);
        }
        uint32_t base = smb + par * BUFB;
        gemm_chunk(acc, base + aoff, base + 10240 + aoff,
                        base + 20480 + boff, base + 30720 + boff);
        cp_wait();
        __syncthreads();
    }

    float* up = g_upart + (size_t)zz * NB * 9216;
#pragma unroll
    for (int mt = 0; mt < 2; mt++) {
        int m0 = mb * 128 + wm * 32 + mt * 16 + g;
        int m1 = m0 + 8;
        int b0 = m0 / 36, pos0 = m0 % 36;
        int b1i = m1 / 36, pos1 = m1 % 36;
#pragma unroll
        for (int j = 0; j < 4; j++)
#pragma unroll
            for (int h = 0; h < 2; h++) {
                int t = mt * 8 + j * 2 + h;
                int col = ny * 128 + wn * 64 + j * 16 + h * 8 + tg * 2;
                up[(size_t)b0 * 9216 + (size_t)col * 36 + pos0] = acc[t][0];
                up[(size_t)b0 * 9216 + (size_t)(col + 1) * 36 + pos0] = acc[t][1];
                up[(size_t)b1i * 9216 + (size_t)col * 36 + pos1] = acc[t][2];
                up[(size_t)b1i * 9216 + (size_t)(col + 1) * 36 + pos1] = acc[t][3];
            }
    }
}

// ---- squash ----
__global__ void k_squash(const float* __restrict__ pb) {
    int idx = blockIdx.x * blockDim.x + threadIdx.x;
    if (idx >= NB * NR) return;
    int r = idx % NR;
    size_t base = (size_t)idx * 8;
    const size_t UP = (size_t)NB * 9216;
    float e[8];
    float sn = 0.f;
#pragma unroll
    for (int j = 0; j < 8; j++) {
        int oc = (r * 8 + j) / 36;
        float v = g_upart[base + j] + g_upart[UP + base + j]
                + g_upart[2 * UP + base + j] + g_upart[3 * UP + base + j]
                + __ldg(pb + oc);
        e[j] = v;
        sn = fmaf(v, v, sn);
    }
    float f = sqrtf(sn) / (1.0f + sn);
    float4 o0 = make_float4(e[0] * f, e[1] * f, e[2] * f, e[3] * f);
    float4 o1 = make_float4(e[4] * f, e[5] * f, e[6] * f, e[7] * f);
    float4* o = (float4*)(g_u + base);
    o[0] = o0; o[1] = o1;
}

__global__ void __launch_bounds__(160) k_uhat(const float* __restrict__ W) {
    __shared__ float sWT[1280];
    int r = blockIdx.x, t = threadIdx.x;
    for (int j = t; j < 1280; j += 160)
        sWT[j] = W[(size_t)r * 1280 + (j % 160) * 8 + j / 160];
    __syncthreads();
    float w0 = sWT[t], w1 = sWT[160+t], w2 = sWT[320+t], w3 = sWT[480+t];
    float w4 = sWT[640+t], w5 = sWT[800+t], w6 = sWT[960+t], w7 = sWT[1120+t];
#pragma unroll 4
    for (int b = 0; b < NB; b++) {
        const float4* up = (const float4*)(g_u + (size_t)b * 9216 + r * 8);
        float4 ua = up[0], ub = up[1];
        G_UHAT[((size_t)b * NR + r) * 160 + t] =
            ua.x*w0 + ua.y*w1 + ua.z*w2 + ua.w*w3 + ub.x*w4 + ub.y*w5 + ub.z*w6 + ub.w*w7;
    }
}

__global__ void k_softmax() {
    __shared__ float sred[128];
    int c = blockIdx.x, t = threadIdx.x;
    float mx = -1e30f;
    for (int r = t; r < NR; r += 128) mx = fmaxf(mx, g_bij[r * NC2 + c]);
    sred[t] = mx; __syncthreads();
    for (int st = 64; st >= 1; st >>= 1) { if (t < st) sred[t] = fmaxf(sred[t], sred[t + st]); __syncthreads(); }
    mx = sred[0]; __syncthreads();
    float sm = 0.f;
    for (int r = t; r < NR; r += 128) sm += expf(g_bij[r * NC2 + c] - mx);
    sred[t] = sm; __syncthreads();
    for (int st = 64; st >= 1; st >>= 1) { if (t < st) sred[t] += sred[t + st]; __syncthreads(); }
    float inv = 1.0f / sred[0];
    for (int r = t; r < NR; r += 128)
        g_cij[r * NC2 + c] = expf(g_bij[r * NC2 + c] - mx) * inv;
}

__global__ void __launch_bounds__(256) k_sj(float* out, int it) {
    __shared__ float4 sred[64][4];
    int b = blockIdx.x, c = blockIdx.y, t = threadIdx.x;
    int og = t & 3, rg = t >> 2;
    float4 acc = make_float4(0.f, 0.f, 0.f, 0.f);
    if (it == 0) {
        for (int r = rg; r < NR; r += 64) {
            float4 u4 = g_uhat4[(((size_t)b * NR + r) * NC2 + c) * 4 + og];
            acc.x += u4.x; acc.y += u4.y; acc.z += u4.z; acc.w += u4.w;
        }
        const float s = 1.0f / NR;
        acc.x *= s; acc.y *= s; acc.z *= s; acc.w *= s;
    } else {
        for (int r = rg; r < NR; r += 64) {
            float cij = __ldg(g_cij + r * NC2 + c);
            float4 u4 = g_uhat4[(((size_t)b * NR + r) * NC2 + c) * 4 + og];
            acc.x = fmaf(cij, u4.x, acc.x); acc.y = fmaf(cij, u4.y, acc.y);
            acc.z = fmaf(cij, u4.z, acc.z); acc.w = fmaf(cij, u4.w, acc.w);
        }
    }
    sred[rg][og] = acc;
    __syncthreads();
    for (int st = 32; st >= 1; st >>= 1) {
        if (rg < st) {
            float4 o4 = sred[rg + st][og];
            acc.x += o4.x; acc.y += o4.y; acc.z += o4.z; acc.w += o4.w;
            sred[rg][og] = acc;
        }
        __syncthreads();
    }
    if (rg == 0) {
        float4 v;
        v.x = acc.x * fabsf(acc.x) / (1.f + acc.x * acc.x);
        v.y = acc.y * fabsf(acc.y) / (1.f + acc.y * acc.y);
        v.z = acc.z * fabsf(acc.z) / (1.f + acc.z * acc.z);
        v.w = acc.w * fabsf(acc.w) / (1.f + acc.w * acc.w);
        g_v4[(b * NC2 + c) * 4 + og] = v;
        if (out) ((float4*)out)[(b * NC2 + c) * 4 + og] = v;
    }
}

__global__ void __launch_bounds__(256) k_aij(int first) {
    __shared__ float sred[256];
    int r = blockIdx.x, c = blockIdx.y, t = threadIdx.x;
    int og = t & 3, bg = t >> 2;
    float acc = 0.f;
    for (int b = bg; b < NB; b += 64) {
        float4 u4 = g_uhat4[(((size_t)b * NR + r) * NC2 + c) * 4 + og];
        float4 v4 = g_v4[(b * NC2 + c) * 4 + og];
        acc += u4.x * v4.x + u4.y * v4.y + u4.z * v4.z + u4.w * v4.w;
    }
    sred[t] = acc; __syncthreads();
    for (int st = 128; st >= 1; st >>= 1) { if (t < st) sred[t] += sred[t + st]; __syncthreads(); }
    if (t == 0) {
        float a = sred[0] * (1.0f / NB);
        if (first) g_bij[r * NC2 + c] = a;
        else g_bij[r * NC2 + c] += a;
    }
}

__global__ void __launch_bounds__(128) k_cls(const float* __restrict__ w1,
                                             const float* __restrict__ b1,
                                             const float* __restrict__ w2,
                                             const float* __restrict__ b2,
                                             float* out) {
    __shared__ float sfeat[160];
    __shared__ float sred[128];
    int b = blockIdx.x, k = blockIdx.y, t = threadIdx.x;
    for (int j = t; j < 160; j += 128) sfeat[j] = G_V[b * 160 + j];
    __syncthreads();
    float val = 0.f;
    if (t < 100) {
        float acc = __ldg(b1 + k * 100 + t);
        const float* wp = w1 + (size_t)k * 16000 + t;
#pragma unroll 4
        for (int f = 0; f < 160; f++) acc = fmaf(sfeat[f], wp[f * 100], acc);
        val = fmaxf(acc, 0.f) * __ldg(w2 + k * 100 + t);
    }
    sred[t] = val; __syncthreads();
    for (int st = 64; st >= 1; st >>= 1) { if (t < st) sred[t] += sred[t + st]; __syncthreads(); }
    if (t == 0)
        out[40960 + b * NC2 + k] = 1.0f / (1.0f + expf(-(sred[0] + __ldg(b2 + k))));
}

extern "C" void kernel_launch(void* const* d_in, const int* in_sizes, int n_in,
                              void* d_out, int out_size) {
    const float* data    = (const float*)d_in[0];
    const float* conv1_w = (const float*)d_in[1];
    const float* conv1_b = (const float*)d_in[2];
    const float* conv2_w = (const float*)d_in[3];
    const float* conv2_b = (const float*)d_in[4];
    const float* prim_w  = (const float*)d_in[5];
    const float* prim_b  = (const float*)d_in[6];
    const float* W       = (const float*)d_in[7];
    const float* cls_w1  = (const float*)d_in[8];
    const float* cls_b1  = (const float*)d_in[9];
    const float* cls_w2  = (const float*)d_in[10];
    const float* cls_b2  = (const float*)d_in[11];
    float* out = (float*)d_out;

    static int inited = 0;
    if (!inited) {
        cudaFuncSetAttribute(k_conv2mma, cudaFuncAttributeMaxDynamicSharedMemorySize, 2 * BUFB);
        cudaFuncSetAttribute(k_primmma, cudaFuncAttributeMaxDynamicSharedMemorySize, 2 * BUFB);
        inited = 1;
    }

    k_tabs<<<41, 256>>>();
    k_cvt_w2<<<576, 256>>>(conv2_w);
    k_cvt_pw<<<20736, 256>>>(prim_w);
    k_conv1pool<<<1444, 256>>>(data, conv1_w, conv1_b);
    k_conv2mma<<<dim3(12, NB), 256, 2 * BUFB>>>(conv2_b);
    k_pool2n<<<dim3(25, NB), 256>>>();
    k_primmma<<<dim3(72, 2, 4), 256, 2 * BUFB>>>();
    k_squash<<<(NB * NR + 255) / 256, 256>>>(prim_b);
    k_uhat<<<NR, 160>>>(W);

    for (int it = 0; it < 3; it++) {
        if (it > 0) k_softmax<<<NC2, 128>>>();
        k_sj<<<dim3(NB, NC2), 256>>>(it == 2 ? out : nullptr, it);
        if (it < 2) k_aij<<<dim3(NR, NC2), 256>>>(it == 0 ? 1 : 0);
    }
    k_cls<<<dim3(NB, NC2), 128>>>(cls_w1, cls_b1, cls_w2, cls_b2, out);
}